// round 13
// baseline (speedup 1.0000x reference)
#include <cuda_runtime.h>
#include <cuda_fp16.h>
#include <cstdint>
#include <cstddef>

#define NN 2048
#define EPS 1e-5f

// ---------------- device scratch ----------------
__device__ float g_Wcat[512 * 576];
__device__ float g_bcat[576];
__device__ float g_P[2 * NN * 576];
__device__ __align__(16) __half g_Bt[26 * 16384];  // 26 tiles x (hi 16KB | lo 16KB)

__device__ __forceinline__ float warp_sum(float v) {
#pragma unroll
    for (int o = 16; o; o >>= 1) v += __shfl_xor_sync(0xffffffffu, v, o);
    return v;
}
__device__ __forceinline__ float warp_max(float v) {
#pragma unroll
    for (int o = 16; o; o >>= 1) v = fmaxf(v, __shfl_xor_sync(0xffffffffu, v, o));
    return v;
}

#define CP_COMMIT() asm volatile("cp.async.commit_group;" ::: "memory")
#define CP_WAIT0()  asm volatile("cp.async.wait_group 0;" ::: "memory")

__device__ __forceinline__ void ldsm4(unsigned r[4], unsigned addr) {
    asm volatile("ldmatrix.sync.aligned.m8n8.x4.shared.b16 {%0,%1,%2,%3}, [%4];"
                 : "=r"(r[0]), "=r"(r[1]), "=r"(r[2]), "=r"(r[3]) : "r"(addr));
}
__device__ __forceinline__ void mma16816h(float d[4], const unsigned a[4], const unsigned b[2]) {
    asm volatile("mma.sync.aligned.m16n8k16.row.col.f32.f16.f16.f32 "
                 "{%0,%1,%2,%3}, {%4,%5,%6,%7}, {%8,%9}, {%0,%1,%2,%3};"
                 : "+f"(d[0]), "+f"(d[1]), "+f"(d[2]), "+f"(d[3])
                 : "r"(a[0]), "r"(a[1]), "r"(a[2]), "r"(a[3]), "r"(b[0]), "r"(b[1]));
}

__device__ __forceinline__ void split2h(float a, float b, uint32_t& w0, uint32_t& w1) {
    __half a0 = __float2half_rn(a), b0 = __float2half_rn(b);
    __half a1 = __float2half_rn(a - __half2float(a0));
    __half b1 = __float2half_rn(b - __half2float(b0));
    w0 = ((uint32_t)__half_as_ushort(b0) << 16) | (uint32_t)__half_as_ushort(a0);
    w1 = ((uint32_t)__half_as_ushort(b1) << 16) | (uint32_t)__half_as_ushort(a1);
}

// 32-col tiles: 0-7 new_if(gc 320..575), 8-9 att(gc 256..319), 10-17 h1(gc 0..255), 18-25 w2
__device__ __host__ __forceinline__ int tile_gc(int tl) {
    return (tl < 8) ? 320 + tl * 32 : (tl < 10) ? 256 + (tl - 8) * 32
          : (tl < 18) ? (tl - 10) * 32 : (tl - 18) * 32;
}

__global__ void dummy_kernel() {}

// ---------------- K0: pack ----------------
__global__ void pack_kernel(const float* __restrict__ w1, const float* __restrict__ watt,
                            const float* __restrict__ wif, const float* __restrict__ b1,
                            const float* __restrict__ batt, const float* __restrict__ bif,
                            const float* __restrict__ w2) {
    int idx = blockIdx.x * blockDim.x + threadIdx.x;
    if (idx < 512 * 576) {
        int r = idx / 576, c = idx - r * 576;
        g_Wcat[idx] = (c < 256) ? w1[r * 256 + c]
                     : (c < 320) ? watt[r * 64 + (c - 256)]
                                 : wif[r * 256 + (c - 320)];
    }
    if (idx < 576)
        g_bcat[idx] = (idx < 256) ? b1[idx] : (idx < 320) ? batt[idx - 256] : bif[idx - 320];
    if (idx < 26 * 8192) {
        int tl = idx >> 13, rr = idx & 8191;
        int n = rr >> 8, k = rr & 255;
        float w;
        if (tl < 18) {
            int c = tile_gc(tl) + n, r = 512 + k;
            w = (c < 256) ? w1[r * 256 + c]
               : (c < 320) ? watt[r * 64 + (c - 256)]
                           : wif[r * 256 + (c - 320)];
        } else {
            w = w2[k * 256 + (tl - 18) * 32 + n];
        }
        __half v0 = __float2half_rn(w);
        __half v1 = __float2half_rn(w - __half2float(v0));
        int byte = n * 512 + ((k * 2) ^ ((n & 7) << 4));
        size_t base = (size_t)tl * 16384 + (byte >> 1);
        g_Bt[base] = v0;
        g_Bt[base + 8192] = v1;
    }
}

// ---------------- K1: P = x @ Wcat(part) ----------------
__device__ __forceinline__ void micro_fma32(const float* __restrict__ ap,
                                            const float* __restrict__ bp, float acc[4][4]) {
#pragma unroll 8
    for (int k = 0; k < 32; k++) {
        const float* apk = ap + k * 65;
        const float* bpk = bp + k * 65;
        float a0 = apk[0], a1 = apk[1], a2 = apk[2], a3 = apk[3];
        float b0 = bpk[0], b1 = bpk[1], b2 = bpk[2], b3 = bpk[3];
        acc[0][0] += a0*b0; acc[0][1] += a0*b1; acc[0][2] += a0*b2; acc[0][3] += a0*b3;
        acc[1][0] += a1*b0; acc[1][1] += a1*b1; acc[1][2] += a1*b2; acc[1][3] += a1*b3;
        acc[2][0] += a2*b0; acc[2][1] += a2*b1; acc[2][2] += a2*b2; acc[2][3] += a2*b3;
        acc[3][0] += a3*b0; acc[3][1] += a3*b1; acc[3][2] += a3*b2; acc[3][3] += a3*b3;
    }
}
__global__ void __launch_bounds__(256) p_kernel(const float* __restrict__ x) {
    extern __shared__ float sm[];
    float* xs = sm;
    float* wsh = xs + 256 * 65;
    int nb = blockIdx.x, part = blockIdx.y, cg = blockIdx.z;
    int t = threadIdx.x, ty = t >> 4, tx = t & 15;
    {
        int row = t >> 2, k0 = (t & 3) * 64;
        const float* src = x + (size_t)(nb * 64 + row) * 256 + k0;
#pragma unroll
        for (int k = 0; k < 64; k += 4) {
            float4 v = *(const float4*)(src + k);
            xs[(k0+k)*65+row]=v.x; xs[(k0+k+1)*65+row]=v.y;
            xs[(k0+k+2)*65+row]=v.z; xs[(k0+k+3)*65+row]=v.w;
        }
    }
    __syncthreads();
    for (int cc = cg * 3; cc < cg * 3 + 3; cc++) {
        float acc[4][4] = {};
        for (int kp = 0; kp < 8; kp++) {
            {
                int k = t >> 3, cb = (t & 7) * 8;
                const float* src = g_Wcat + (size_t)(part*256 + kp*32 + k)*576 + cc*64 + cb;
                float4 v0 = *(const float4*)src, v1 = *(const float4*)(src + 4);
                float* d = wsh + k*65 + cb;
                d[0]=v0.x; d[1]=v0.y; d[2]=v0.z; d[3]=v0.w;
                d[4]=v1.x; d[5]=v1.y; d[6]=v1.z; d[7]=v1.w;
            }
            __syncthreads();
            micro_fma32(xs + kp*32*65 + ty*4, wsh + tx*4, acc);
            __syncthreads();
        }
#pragma unroll
        for (int ri = 0; ri < 4; ri++) {
            float4 v = make_float4(acc[ri][0], acc[ri][1], acc[ri][2], acc[ri][3]);
            *(float4*)(g_P + (size_t)part*NN*576 + (size_t)(nb*64 + ty*4 + ri)*576 + cc*64 + tx*4) = v;
        }
    }
}

// ---------------- K2: fused per-site kernel, 512 threads, k-split warp pairs ----------------
// smem (bytes): [16..528) idxs; A imgs 1024 / 33792 (32KB each);
// B dbl buf 66560 / 99328 (32KB each); tbuf 132096 [64][260]; afb 198656 [64][66];
// scr 215552 (8KB partial-accumulator scratch). Total 223744.
__global__ void __launch_bounds__(512) big_kernel(
    const float* __restrict__ IF, const int* __restrict__ ai, const int* __restrict__ aj,
    const float* __restrict__ g1, const float* __restrict__ be1,
    const float* __restrict__ gatt, const float* __restrict__ beatt,
    const float* __restrict__ gif, const float* __restrict__ beif,
    const float* __restrict__ b2, const float* __restrict__ g2, const float* __restrict__ be2,
    const float* __restrict__ wpre, const float* __restrict__ bpre,
    const int* __restrict__ mask,
    const float* __restrict__ wg, const float* __restrict__ bg,
    const float* __restrict__ gg, const float* __restrict__ beg,
    float* __restrict__ out) {
    extern __shared__ char smem[];
    const unsigned sb = (unsigned)__cvta_generic_to_shared(smem);
    int* idxs = (int*)(smem + 16);
    char* Agen = smem + 1024;
    const unsigned Abase = sb + 1024;
    const unsigned Bb[2] = { sb + 66560, sb + 99328 };
    float* tbuf = (float*)(smem + 132096);   // [64][260]
    float* afb  = (float*)(smem + 198656);   // [64][66]
    float* scr  = (float*)(smem + 215552);   // [8 pairs][32 lanes][8]
    float* slog = (float*)(smem + 66560);    // aliases after GEMMs
    float* wsm  = (float*)(smem + 67584);
    float* aggs = (float*)(smem + 68608);
    float* red  = (float*)(smem + 69632);

    const int n = blockIdx.x, t = threadIdx.x;
    const int lane = t & 31, wid = t >> 5;
    const int pairid = wid & 7, khalf = wid >> 3;
    const int mrow0 = (pairid >> 1) << 4;
    const int nh16 = (pairid & 1) << 4;
    const float NEG = __int_as_float(0xff800000);
    const float inv256 = 1.f / 256.f, inv64 = 1.f / 64.f;

    // ldmatrix geometry
    const int arow = mrow0 + (lane & 15);
    const unsigned abase_off = (unsigned)(arow * 512);
    const unsigned asw = (unsigned)((arow & 7) << 4);
    const unsigned achunk = (unsigned)((lane >> 4) << 4);
    const int brow = nh16 + ((lane >> 4) << 3) + (lane & 7);
    const unsigned bbase_off = (unsigned)(brow * 512);
    const unsigned bsw = (unsigned)((brow & 7) << 4);
    const unsigned bchunk = (unsigned)(((lane >> 3) & 1) << 4);
    // epilogue geometry
    const int eg = lane >> 2, etig = lane & 3;
    const int er0 = mrow0 + eg, er1 = mrow0 + eg + 8;

    if (t < 64) { idxs[t] = ai[n * 64 + t]; idxs[64 + t] = aj[n * 64 + t]; }

    // prefetch B tile 0 (hi image only, 16KB) — 512 threads x 16B x 2
    {
        const char* src = (const char*)g_Bt;
#pragma unroll
        for (int i = 0; i < 2; i++) {
            unsigned off = (unsigned)(i * 8192 + t * 16);
            asm volatile("cp.async.cg.shared.global [%0], [%1], 16;" :: "r"(Bb[0] + off), "l"(src + off) : "memory");
        }
        CP_COMMIT();
    }

    // convert IF -> A (2 fp16 images, swizzled); 512 threads, 32 k each
    {
        int row = t >> 3, k0 = (t & 7) * 32;
        const float* src = IF + (size_t)(n * 64 + row) * 256 + k0;
#pragma unroll
        for (int c = 0; c < 4; c++) {
            float4 v0 = *(const float4*)(src + c * 8);
            float4 v1 = *(const float4*)(src + c * 8 + 4);
            uint4 i0, i1;
            split2h(v0.x, v0.y, i0.x, i1.x);
            split2h(v0.z, v0.w, i0.y, i1.y);
            split2h(v1.x, v1.y, i0.z, i1.z);
            split2h(v1.z, v1.w, i0.w, i1.w);
            unsigned off = (unsigned)(row * 512 + (((k0 + c * 8) * 2) ^ ((row & 7) << 4)));
            *(uint4*)(Agen + off) = i0;
            *(uint4*)(Agen + 32768 + off) = i1;
        }
    }

    // ================= main tile loop =================
#pragma unroll 1
    for (int tl = 0; tl < 26; tl++) {
        CP_WAIT0();
        __syncthreads();     // B[tl] visible; mma(tl-1) and scratch(tl-1) consumed

        if (tl < 25) {
            const char* src = (const char*)g_Bt + (size_t)(tl + 1) * 32768;
            unsigned dst = Bb[(tl + 1) & 1];
            int nch = (tl + 1 < 10) ? 2 : 4;
#pragma unroll 1
            for (int i = 0; i < nch; i++) {
                unsigned off = (unsigned)(i * 8192 + t * 16);
                asm volatile("cp.async.cg.shared.global [%0], [%1], 16;" :: "r"(dst + off), "l"(src + off) : "memory");
            }
            CP_COMMIT();
        }

        // epilogue operand prefetch (only consumer warps)
        float2 p_pi0[2], p_pj0[2], p_pi1[2], p_pj1[2], p_bb[2];
        if (wid < 8) {
            int gc_e = tile_gc(tl);
            if (tl < 18) {
#pragma unroll
                for (int j = 0; j < 2; j++) {
                    int colg = gc_e + nh16 + j * 8 + 2 * etig;
                    p_bb[j]  = *(const float2*)(g_bcat + colg);
                    p_pi0[j] = *(const float2*)(g_P + (size_t)idxs[er0] * 576 + colg);
                    p_pj0[j] = *(const float2*)(g_P + (size_t)NN * 576 + (size_t)idxs[64 + er0] * 576 + colg);
                    p_pi1[j] = *(const float2*)(g_P + (size_t)idxs[er1] * 576 + colg);
                    p_pj1[j] = *(const float2*)(g_P + (size_t)NN * 576 + (size_t)idxs[64 + er1] * 576 + colg);
                }
            } else {
#pragma unroll
                for (int j = 0; j < 2; j++) {
                    int colg = gc_e + nh16 + j * 8 + 2 * etig;
                    p_bb[j]  = *(const float2*)(b2 + colg);
                    p_pi0[j] = p_pj0[j] = p_pi1[j] = p_pj1[j] = make_float2(0.f, 0.f);
                }
            }
        }

        // ---- k-split mma: this warp handles ks = khalf, khalf+2, ... ----
        const bool full = (tl >= 10);
        float dd[6][4] = {};
        const unsigned Bt0 = Bb[tl & 1];
#pragma unroll 8
        for (int ks = khalf; ks < 16; ks += 2) {
            unsigned kb = (unsigned)(ks << 5);
            unsigned aoff = abase_off + ((kb + achunk) ^ asw);
            unsigned boff = bbase_off + ((kb + bchunk) ^ bsw);
            unsigned a0[4], a1[4], b0[4];
            ldsm4(a0, Abase + aoff);
            ldsm4(a1, Abase + 32768 + aoff);
            ldsm4(b0, Bt0 + boff);
            mma16816h(dd[0], a0, b0);
            mma16816h(dd[1], a1, b0);
            mma16816h(dd[3], a0, b0 + 2);
            mma16816h(dd[4], a1, b0 + 2);
            if (full) {
                unsigned b1[4];
                ldsm4(b1, Bt0 + 16384 + boff);
                mma16816h(dd[2], a0, b1);
                mma16816h(dd[5], a0, b1 + 2);
            }
        }

        // term-combine
        float ee[2][4];
#pragma unroll
        for (int j = 0; j < 2; j++)
#pragma unroll
            for (int c = 0; c < 4; c++)
                ee[j][c] = dd[j*3][c] + dd[j*3+1][c] + dd[j*3+2][c];

        // partner (khalf=1) publishes partials
        if (wid >= 8) {
            float* s = scr + (pairid * 32 + lane) * 8;
#pragma unroll
            for (int j = 0; j < 2; j++)
#pragma unroll
                for (int c = 0; c < 4; c++) s[j * 4 + c] = ee[j][c];
        }
        __syncthreads();

        // consumer warps combine + epilogue
        if (wid < 8) {
            const float* s = scr + (pairid * 32 + lane) * 8;
#pragma unroll
            for (int j = 0; j < 2; j++)
#pragma unroll
                for (int c = 0; c < 4; c++) ee[j][c] += s[j * 4 + c];

            float* dst; int dstride, dcol;
            if (tl < 8)       { dst = tbuf; dstride = 260; dcol = tl * 32; }
            else if (tl < 10) { dst = afb;  dstride = 66;  dcol = (tl - 8) * 32; }
            else if (tl < 18) { dst = tbuf; dstride = 260; dcol = (tl - 10) * 32; }
            else              { dst = tbuf; dstride = 260; dcol = (tl - 18) * 32; }
#pragma unroll
            for (int j = 0; j < 2; j++) {
                int dc = dcol + nh16 + j * 8 + 2 * etig;
                *(float2*)(dst + (size_t)er0 * dstride + dc) =
                    make_float2(ee[j][0] + p_pi0[j].x + p_pj0[j].x + p_bb[j].x,
                                ee[j][1] + p_pi0[j].y + p_pj0[j].y + p_bb[j].y);
                *(float2*)(dst + (size_t)er1 * dstride + dc) =
                    make_float2(ee[j][2] + p_pi1[j].x + p_pj1[j].x + p_bb[j].x,
                                ee[j][3] + p_pi1[j].y + p_pj1[j].y + p_bb[j].y);
            }
        }

        // ---- segment boundaries ----
        if (tl == 7) {
            __syncthreads();
#pragma unroll 1
            for (int rr = 0; rr < 4; rr++) {
                int row = rr * 16 + wid;
                const float* trow = tbuf + row * 260;
                float v[8], s = 0.f, qq = 0.f;
#pragma unroll
                for (int j = 0; j < 8; j++) {
                    float xv = fmaxf(trow[lane + j * 32], 0.f);
                    v[j] = xv; s += xv; qq += xv * xv;
                }
                s = warp_sum(s); qq = warp_sum(qq);
                float mu = s * inv256, rstd = rsqrtf(qq * inv256 - mu * mu + EPS);
                float* o = out + 524288 + ((size_t)n * 64 + row) * 256;
#pragma unroll
                for (int j = 0; j < 8; j++) {
                    int c = lane + j * 32;
                    o[c] = (v[j] - mu) * rstd * gif[c] + beif[c];
                }
            }
        }
        if (tl == 17) {
            __syncthreads();
#pragma unroll 1
            for (int rr = 0; rr < 4; rr++) {
                int row = rr * 16 + wid;
                {
                    float* ar = afb + row * 66;
                    float x0 = fmaxf(ar[lane], 0.f), x1 = fmaxf(ar[32 + lane], 0.f);
                    float s = warp_sum(x0 + x1), qq = warp_sum(x0 * x0 + x1 * x1);
                    float mu = s * inv64, rstd = rsqrtf(qq * inv64 - mu * mu + EPS);
                    ar[lane] = (x0 - mu) * rstd * gatt[lane] + beatt[lane];
                    ar[32 + lane] = (x1 - mu) * rstd * gatt[32 + lane] + beatt[32 + lane];
                }
                {
                    float* trow = tbuf + row * 260;
                    float v[8], s = 0.f, qq = 0.f;
#pragma unroll
                    for (int j = 0; j < 8; j++) {
                        float xv = fmaxf(trow[lane + j * 32], 0.f);
                        v[j] = xv; s += xv; qq += xv * xv;
                    }
                    s = warp_sum(s); qq = warp_sum(qq);
                    float mu = s * inv256, rstd = rsqrtf(qq * inv256 - mu * mu + EPS);
#pragma unroll
                    for (int j = 0; j < 8; j++) {
                        int c = lane + j * 32;
                        trow[c] = (v[j] - mu) * rstd * g1[c] + be1[c];
                    }
                }
            }
            __syncthreads();
            // rewrite A = h1 (2 fp16 images), 512 threads
            {
                int row = t >> 3, k0 = (t & 7) * 32;
                const float* src = tbuf + row * 260 + k0;
#pragma unroll
                for (int c = 0; c < 4; c++) {
                    float4 v0 = *(const float4*)(src + c * 8);
                    float4 v1 = *(const float4*)(src + c * 8 + 4);
                    uint4 i0, i1;
                    split2h(v0.x, v0.y, i0.x, i1.x);
                    split2h(v0.z, v0.w, i0.y, i1.y);
                    split2h(v1.x, v1.y, i0.z, i1.z);
                    split2h(v1.z, v1.w, i0.w, i1.w);
                    unsigned off = (unsigned)(row * 512 + (((k0 + c * 8) * 2) ^ ((row & 7) << 4)));
                    *(uint4*)(Agen + off) = i0;
                    *(uint4*)(Agen + 32768 + off) = i1;
                }
            }
            __syncthreads();
        }
    }
    __syncthreads();

    // ---- Phase 4: h2 = LN(relu(t2)); logits -> slog ----
#pragma unroll 1
    for (int rr = 0; rr < 4; rr++) {
        int row = rr * 16 + wid;
        const float* trow = tbuf + row * 260;
        float v[8], s = 0.f, qq = 0.f;
#pragma unroll
        for (int j = 0; j < 8; j++) {
            float xv = fmaxf(trow[lane + j * 32], 0.f);
            v[j] = xv; s += xv; qq += xv * xv;
        }
        s = warp_sum(s); qq = warp_sum(qq);
        float mu = s * inv256, rstd = rsqrtf(qq * inv256 - mu * mu + EPS);
        float l0 = 0.f, l1 = 0.f, l2 = 0.f, l3 = 0.f;
#pragma unroll
        for (int j = 0; j < 8; j++) {
            int c = lane + j * 32;
            float y = (v[j] - mu) * rstd * g2[c] + be2[c];
            float4 wp = *(const float4*)(wpre + (size_t)c * 4);
            l0 += y * wp.x; l1 += y * wp.y; l2 += y * wp.z; l3 += y * wp.w;
        }
        l0 = warp_sum(l0); l1 = warp_sum(l1); l2 = warp_sum(l2); l3 = warp_sum(l3);
        if (lane == 0) {
            bool mk = mask[n * 64 + row] != 0;
            slog[row * 4 + 0] = mk ? NEG : (l0 + bpre[0]);
            slog[row * 4 + 1] = mk ? NEG : (l1 + bpre[1]);
            slog[row * 4 + 2] = mk ? NEG : (l2 + bpre[2]);
            slog[row * 4 + 3] = mk ? NEG : (l3 + bpre[3]);
        }
    }
    __syncthreads();

    // ---- Phase 5: per-head top-16 softmax ----
    if (wid < 4) {
        int h = wid;
        float v0 = slog[lane * 4 + h], v1 = slog[(32 + lane) * 4 + h];
        float c0 = v0, c1 = v1;
        float thr = NEG, maxv = NEG;
#pragma unroll 1
        for (int it = 0; it < 16; it++) {
            float loc = fmaxf(c0, c1);
            float m = warp_max(loc);
            if (it == 0) maxv = m;
            if (m == NEG) break;
            thr = m;
            unsigned bl = __ballot_sync(0xffffffffu, loc == m);
            int src = __ffs(bl) - 1;
            if (lane == src) { if (c0 == m) c0 = NEG; else c1 = NEG; }
        }
        float e0 = (v0 >= thr) ? expf(v0 - maxv) : 0.f;
        float e1 = (v1 >= thr) ? expf(v1 - maxv) : 0.f;
        float inv = 1.f / warp_sum(e0 + e1);
        wsm[h * 64 + lane] = e0 * inv;
        wsm[h * 64 + 32 + lane] = e1 * inv;
    }
    __syncthreads();

    // ---- Phase 6: agg[d,h] = sum_m w[h,m] * af[m,d] ----
    if (t < 256) {
        int d = t >> 2, h = t & 3;
        float s = 0.f;
#pragma unroll
        for (int m = 0; m < 64; m++) s += wsm[h * 64 + m] * afb[m * 66 + d];
        aggs[t] = s;
    }
    __syncthreads();

    // ---- Phase 7: x_out = LN(relu(agg @ wg + bg)) ----
    {
        float v = 0.f;
        if (t < 256) {
            float v0a = 0.f, v1a = 0.f, v2a = 0.f, v3a = 0.f;
            float v4a = 0.f, v5a = 0.f, v6a = 0.f, v7a = 0.f;
#pragma unroll 4
            for (int k = 0; k < 256; k += 8) {
                v0a += aggs[k]     * wg[(size_t)k * 256 + t];
                v1a += aggs[k + 1] * wg[(size_t)(k + 1) * 256 + t];
                v2a += aggs[k + 2] * wg[(size_t)(k + 2) * 256 + t];
                v3a += aggs[k + 3] * wg[(size_t)(k + 3) * 256 + t];
                v4a += aggs[k + 4] * wg[(size_t)(k + 4) * 256 + t];
                v5a += aggs[k + 5] * wg[(size_t)(k + 5) * 256 + t];
                v6a += aggs[k + 6] * wg[(size_t)(k + 6) * 256 + t];
                v7a += aggs[k + 7] * wg[(size_t)(k + 7) * 256 + t];
            }
            v = fmaxf(((v0a + v1a) + (v2a + v3a)) + ((v4a + v5a) + (v6a + v7a)) + bg[t], 0.f);
        }
        float s = warp_sum(v), qq = warp_sum(v * v);
        if (lane == 0 && wid < 8) { red[wid] = s; red[8 + wid] = qq; }
        __syncthreads();
        if (t < 32) {
            float a = (lane < 8) ? red[lane] : 0.f;
            float b = (lane < 8) ? red[8 + lane] : 0.f;
#pragma unroll
            for (int o = 4; o; o >>= 1) {
                a += __shfl_xor_sync(0xffffffffu, a, o);
                b += __shfl_xor_sync(0xffffffffu, b, o);
            }
            if (lane == 0) { red[0] = a; red[8] = b; }
        }
        __syncthreads();
        if (t < 256) {
            float mu = red[0] * inv256, rstd = rsqrtf(red[8] * inv256 - mu * mu + EPS);
            float y = (v - mu) * rstd * gg[t] + beg[t];
            out[(size_t)n * 256 + t] = y;
            out[34078720ull + (size_t)n * 256 + t] = y;
        }
    }
}

// ---------------- launch ----------------
extern "C" void kernel_launch(void* const* d_in, const int* in_sizes, int n_in,
                              void* d_out, int out_size) {
    const float* x = (const float*)d_in[0];
    const float* iff = (const float*)d_in[1];
    const int* mask = (const int*)d_in[2];
    const int* ai = (const int*)d_in[3];
    const int* aj = (const int*)d_in[4];
    const float* w1 = (const float*)d_in[5], *b1 = (const float*)d_in[6];
    const float* g1 = (const float*)d_in[7], *be1 = (const float*)d_in[8];
    const float* w2 = (const float*)d_in[9], *b2 = (const float*)d_in[10];
    const float* g2 = (const float*)d_in[11], *be2 = (const float*)d_in[12];
    const float* wpre = (const float*)d_in[13], *bpre = (const float*)d_in[14];
    const float* watt = (const float*)d_in[15], *batt = (const float*)d_in[16];
    const float* gatt = (const float*)d_in[17], *beatt = (const float*)d_in[18];
    const float* wif = (const float*)d_in[19], *bif = (const float*)d_in[20];
    const float* gif = (const float*)d_in[21], *beif = (const float*)d_in[22];
    const float* wg = (const float*)d_in[23], *bg = (const float*)d_in[24];
    const float* gg = (const float*)d_in[25], *beg = (const float*)d_in[26];
    float* out = (float*)d_out;

    const int PS = (256 * 65 + 32 * 65) * 4;
    const int BS = 223744;
    cudaFuncSetAttribute(p_kernel, cudaFuncAttributeMaxDynamicSharedMemorySize, PS);
    cudaFuncSetAttribute(big_kernel, cudaFuncAttributeMaxDynamicSharedMemorySize, BS);

    dummy_kernel<<<1, 32>>>();
    pack_kernel<<<1152, 256>>>(w1, watt, wif, b1, batt, bif, w2);
    p_kernel<<<dim3(32, 2, 3), 256, PS>>>(x);
    big_kernel<<<2048, 512, BS>>>(iff, ai, aj, g1, be1, gatt, beatt, gif, beif,
                                  b2, g2, be2, wpre, bpre, mask,
                                  wg, bg, gg, beg, out);
}

// round 14
// speedup vs baseline: 1.4955x; 1.4955x over previous
#include <cuda_runtime.h>
#include <cuda_fp16.h>
#include <cstdint>
#include <cstddef>

#define NN 2048
#define EPS 1e-5f

// ---------------- device scratch ----------------
__device__ float g_Wcat[512 * 576];
__device__ float g_bcat[576];
__device__ float g_P[2 * NN * 576];
__device__ __align__(16) __half g_Bt[26 * 16384];  // 26 tiles x (hi 16KB | lo 16KB)

__device__ __forceinline__ float warp_sum(float v) {
#pragma unroll
    for (int o = 16; o; o >>= 1) v += __shfl_xor_sync(0xffffffffu, v, o);
    return v;
}
__device__ __forceinline__ float warp_max(float v) {
#pragma unroll
    for (int o = 16; o; o >>= 1) v = fmaxf(v, __shfl_xor_sync(0xffffffffu, v, o));
    return v;
}

#define CP_COMMIT() asm volatile("cp.async.commit_group;" ::: "memory")
#define CP_WAIT0()  asm volatile("cp.async.wait_group 0;" ::: "memory")

__device__ __forceinline__ void ldsm4(unsigned r[4], unsigned addr) {
    asm volatile("ldmatrix.sync.aligned.m8n8.x4.shared.b16 {%0,%1,%2,%3}, [%4];"
                 : "=r"(r[0]), "=r"(r[1]), "=r"(r[2]), "=r"(r[3]) : "r"(addr));
}
__device__ __forceinline__ void mma16816h(float d[4], const unsigned a[4], const unsigned b[2]) {
    asm volatile("mma.sync.aligned.m16n8k16.row.col.f32.f16.f16.f32 "
                 "{%0,%1,%2,%3}, {%4,%5,%6,%7}, {%8,%9}, {%0,%1,%2,%3};"
                 : "+f"(d[0]), "+f"(d[1]), "+f"(d[2]), "+f"(d[3])
                 : "r"(a[0]), "r"(a[1]), "r"(a[2]), "r"(a[3]), "r"(b[0]), "r"(b[1]));
}

__device__ __forceinline__ void split2h(float a, float b, uint32_t& w0, uint32_t& w1) {
    __half a0 = __float2half_rn(a), b0 = __float2half_rn(b);
    __half a1 = __float2half_rn(a - __half2float(a0));
    __half b1 = __float2half_rn(b - __half2float(b0));
    w0 = ((uint32_t)__half_as_ushort(b0) << 16) | (uint32_t)__half_as_ushort(a0);
    w1 = ((uint32_t)__half_as_ushort(b1) << 16) | (uint32_t)__half_as_ushort(a1);
}

// 32-col tiles: 0-7 new_if(gc 320..575), 8-9 att(gc 256..319), 10-17 h1(gc 0..255), 18-25 w2
__device__ __host__ __forceinline__ int tile_gc(int tl) {
    return (tl < 8) ? 320 + tl * 32 : (tl < 10) ? 256 + (tl - 8) * 32
          : (tl < 18) ? (tl - 10) * 32 : (tl - 18) * 32;
}

__global__ void dummy_kernel() {}

// ---------------- K0: pack ----------------
__global__ void pack_kernel(const float* __restrict__ w1, const float* __restrict__ watt,
                            const float* __restrict__ wif, const float* __restrict__ b1,
                            const float* __restrict__ batt, const float* __restrict__ bif,
                            const float* __restrict__ w2) {
    int idx = blockIdx.x * blockDim.x + threadIdx.x;
    if (idx < 512 * 576) {
        int r = idx / 576, c = idx - r * 576;
        g_Wcat[idx] = (c < 256) ? w1[r * 256 + c]
                     : (c < 320) ? watt[r * 64 + (c - 256)]
                                 : wif[r * 256 + (c - 320)];
    }
    if (idx < 576)
        g_bcat[idx] = (idx < 256) ? b1[idx] : (idx < 320) ? batt[idx - 256] : bif[idx - 320];
    if (idx < 26 * 8192) {
        int tl = idx >> 13, rr = idx & 8191;
        int n = rr >> 8, k = rr & 255;
        float w;
        if (tl < 18) {
            int c = tile_gc(tl) + n, r = 512 + k;
            w = (c < 256) ? w1[r * 256 + c]
               : (c < 320) ? watt[r * 64 + (c - 256)]
                           : wif[r * 256 + (c - 320)];
        } else {
            w = w2[k * 256 + (tl - 18) * 32 + n];
        }
        __half v0 = __float2half_rn(w);
        __half v1 = __float2half_rn(w - __half2float(v0));
        int byte = n * 512 + ((k * 2) ^ ((n & 7) << 4));
        size_t base = (size_t)tl * 16384 + (byte >> 1);
        g_Bt[base] = v0;
        g_Bt[base + 8192] = v1;
    }
}

// ---------------- K1: P = x @ Wcat(part) ----------------
__device__ __forceinline__ void micro_fma32(const float* __restrict__ ap,
                                            const float* __restrict__ bp, float acc[4][4]) {
#pragma unroll 8
    for (int k = 0; k < 32; k++) {
        const float* apk = ap + k * 65;
        const float* bpk = bp + k * 65;
        float a0 = apk[0], a1 = apk[1], a2 = apk[2], a3 = apk[3];
        float b0 = bpk[0], b1 = bpk[1], b2 = bpk[2], b3 = bpk[3];
        acc[0][0] += a0*b0; acc[0][1] += a0*b1; acc[0][2] += a0*b2; acc[0][3] += a0*b3;
        acc[1][0] += a1*b0; acc[1][1] += a1*b1; acc[1][2] += a1*b2; acc[1][3] += a1*b3;
        acc[2][0] += a2*b0; acc[2][1] += a2*b1; acc[2][2] += a2*b2; acc[2][3] += a2*b3;
        acc[3][0] += a3*b0; acc[3][1] += a3*b1; acc[3][2] += a3*b2; acc[3][3] += a3*b3;
    }
}
__global__ void __launch_bounds__(256) p_kernel(const float* __restrict__ x) {
    extern __shared__ float sm[];
    float* xs = sm;
    float* wsh = xs + 256 * 65;
    int nb = blockIdx.x, part = blockIdx.y, cg = blockIdx.z;
    int t = threadIdx.x, ty = t >> 4, tx = t & 15;
    {
        int row = t >> 2, k0 = (t & 3) * 64;
        const float* src = x + (size_t)(nb * 64 + row) * 256 + k0;
#pragma unroll
        for (int k = 0; k < 64; k += 4) {
            float4 v = *(const float4*)(src + k);
            xs[(k0+k)*65+row]=v.x; xs[(k0+k+1)*65+row]=v.y;
            xs[(k0+k+2)*65+row]=v.z; xs[(k0+k+3)*65+row]=v.w;
        }
    }
    __syncthreads();
    for (int cc = cg * 3; cc < cg * 3 + 3; cc++) {
        float acc[4][4] = {};
        for (int kp = 0; kp < 8; kp++) {
            {
                int k = t >> 3, cb = (t & 7) * 8;
                const float* src = g_Wcat + (size_t)(part*256 + kp*32 + k)*576 + cc*64 + cb;
                float4 v0 = *(const float4*)src, v1 = *(const float4*)(src + 4);
                float* d = wsh + k*65 + cb;
                d[0]=v0.x; d[1]=v0.y; d[2]=v0.z; d[3]=v0.w;
                d[4]=v1.x; d[5]=v1.y; d[6]=v1.z; d[7]=v1.w;
            }
            __syncthreads();
            micro_fma32(xs + kp*32*65 + ty*4, wsh + tx*4, acc);
            __syncthreads();
        }
#pragma unroll
        for (int ri = 0; ri < 4; ri++) {
            float4 v = make_float4(acc[ri][0], acc[ri][1], acc[ri][2], acc[ri][3]);
            *(float4*)(g_P + (size_t)part*NN*576 + (size_t)(nb*64 + ty*4 + ri)*576 + cc*64 + tx*4) = v;
        }
    }
}

// ---------------- K2: fused per-site kernel (R12 structure + split accumulators) ----------------
// smem (bytes): [16..528) idxs; A imgs at 1024 / 33792 (32KB each);
// B dbl buf 66560 / 99328 (32768 each); tbuf 132096 [64][260] fp32; afb 198656 [64][66].
__global__ void __launch_bounds__(256) big_kernel(
    const float* __restrict__ IF, const int* __restrict__ ai, const int* __restrict__ aj,
    const float* __restrict__ g1, const float* __restrict__ be1,
    const float* __restrict__ gatt, const float* __restrict__ beatt,
    const float* __restrict__ gif, const float* __restrict__ beif,
    const float* __restrict__ b2, const float* __restrict__ g2, const float* __restrict__ be2,
    const float* __restrict__ wpre, const float* __restrict__ bpre,
    const int* __restrict__ mask,
    const float* __restrict__ wg, const float* __restrict__ bg,
    const float* __restrict__ gg, const float* __restrict__ beg,
    float* __restrict__ out) {
    extern __shared__ char smem[];
    const unsigned sb = (unsigned)__cvta_generic_to_shared(smem);
    int* idxs = (int*)(smem + 16);
    char* Agen = smem + 1024;
    const unsigned Abase = sb + 1024;
    const unsigned Bb[2] = { sb + 66560, sb + 99328 };
    float* tbuf = (float*)(smem + 132096);   // [64][260]
    float* afb  = (float*)(smem + 198656);   // [64][66]
    float* slog = (float*)(smem + 66560);    // aliases, used after GEMMs
    float* wsm  = (float*)(smem + 67584);
    float* aggs = (float*)(smem + 68608);
    float* red  = (float*)(smem + 69632);

    const int n = blockIdx.x, t = threadIdx.x;
    const int lane = t & 31, wid = t >> 5;
    const int mrow0 = (wid >> 1) << 4;       // M16 group
    const int nh16 = (wid & 1) << 4;         // N16 half within 32-col tile
    const float NEG = __int_as_float(0xff800000);
    const float inv256 = 1.f / 256.f, inv64 = 1.f / 64.f;

    // ldmatrix geometry: A fragment (m16k16)
    const int arow = mrow0 + (lane & 15);
    const unsigned abase_off = (unsigned)(arow * 512);
    const unsigned asw = (unsigned)((arow & 7) << 4);
    const unsigned achunk = (unsigned)((lane >> 4) << 4);
    // B fragment (n16k16)
    const int brow = nh16 + ((lane >> 4) << 3) + (lane & 7);
    const unsigned bbase_off = (unsigned)(brow * 512);
    const unsigned bsw = (unsigned)((brow & 7) << 4);
    const unsigned bchunk = (unsigned)(((lane >> 3) & 1) << 4);
    // epilogue geometry (lane-constant)
    const int eg = lane >> 2, etig = lane & 3;
    const int er0 = mrow0 + eg, er1 = mrow0 + eg + 8;

    if (t < 64) { idxs[t] = ai[n * 64 + t]; idxs[64 + t] = aj[n * 64 + t]; }

    // prefetch B tile 0 (2-term tile: hi image only, 16KB)
    {
        const char* src = (const char*)g_Bt;
#pragma unroll
        for (int i = 0; i < 4; i++) {
            unsigned off = (unsigned)(i * 4096 + t * 16);
            asm volatile("cp.async.cg.shared.global [%0], [%1], 16;" :: "r"(Bb[0] + off), "l"(src + off) : "memory");
        }
        CP_COMMIT();
    }

    // convert IF -> A (2 fp16 images, swizzled)
    {
        int row = t >> 2, k0 = (t & 3) * 64;
        const float* src = IF + (size_t)(n * 64 + row) * 256 + k0;
#pragma unroll
        for (int c = 0; c < 8; c++) {
            float4 v0 = *(const float4*)(src + c * 8);
            float4 v1 = *(const float4*)(src + c * 8 + 4);
            uint4 i0, i1;
            split2h(v0.x, v0.y, i0.x, i1.x);
            split2h(v0.z, v0.w, i0.y, i1.y);
            split2h(v1.x, v1.y, i0.z, i1.z);
            split2h(v1.z, v1.w, i0.w, i1.w);
            unsigned off = (unsigned)(row * 512 + (((k0 + c * 8) * 2) ^ ((row & 7) << 4)));
            *(uint4*)(Agen + off) = i0;
            *(uint4*)(Agen + 32768 + off) = i1;
        }
    }

    // ================= main tile loop (26 tiles), ONE sync per tile =================
#pragma unroll 1
    for (int tl = 0; tl < 26; tl++) {
        CP_WAIT0();
        __syncthreads();     // B[tl] visible; all warps done with mma(tl-1)

        if (tl < 25) {
            const char* src = (const char*)g_Bt + (size_t)(tl + 1) * 32768;
            unsigned dst = Bb[(tl + 1) & 1];
            int nch = (tl + 1 < 10) ? 4 : 8;
#pragma unroll 1
            for (int i = 0; i < nch; i++) {
                unsigned off = (unsigned)(i * 4096 + t * 16);
                asm volatile("cp.async.cg.shared.global [%0], [%1], 16;" :: "r"(dst + off), "l"(src + off) : "memory");
            }
            CP_COMMIT();
        }

        // ---- register-prefetch epilogue operands ----
        float2 p_pi0[2], p_pj0[2], p_pi1[2], p_pj1[2], p_bb[2];
        {
            int gc_e = tile_gc(tl);
            if (tl < 18) {
#pragma unroll
                for (int j = 0; j < 2; j++) {
                    int colg = gc_e + nh16 + j * 8 + 2 * etig;
                    p_bb[j]  = *(const float2*)(g_bcat + colg);
                    p_pi0[j] = *(const float2*)(g_P + (size_t)idxs[er0] * 576 + colg);
                    p_pj0[j] = *(const float2*)(g_P + (size_t)NN * 576 + (size_t)idxs[64 + er0] * 576 + colg);
                    p_pi1[j] = *(const float2*)(g_P + (size_t)idxs[er1] * 576 + colg);
                    p_pj1[j] = *(const float2*)(g_P + (size_t)NN * 576 + (size_t)idxs[64 + er1] * 576 + colg);
                }
            } else {
#pragma unroll
                for (int j = 0; j < 2; j++) {
                    int colg = gc_e + nh16 + j * 8 + 2 * etig;
                    p_bb[j]  = *(const float2*)(b2 + colg);
                    p_pi0[j] = p_pj0[j] = p_pi1[j] = p_pj1[j] = make_float2(0.f, 0.f);
                }
            }
        }

        // ---- mma with SPLIT accumulators: even-ks -> da, odd-ks -> db (12 chains) ----
        const bool full = (tl >= 10);
        float da[6][4] = {}, db[6][4] = {};
        const unsigned Bt0 = Bb[tl & 1];
#pragma unroll 4
        for (int kp = 0; kp < 8; kp++) {
            // even ks = 2*kp
            {
                unsigned kb = (unsigned)((2 * kp) << 5);
                unsigned aoff = abase_off + ((kb + achunk) ^ asw);
                unsigned boff = bbase_off + ((kb + bchunk) ^ bsw);
                unsigned a0[4], a1[4], b0[4];
                ldsm4(a0, Abase + aoff);
                ldsm4(a1, Abase + 32768 + aoff);
                ldsm4(b0, Bt0 + boff);
                mma16816h(da[0], a0, b0);
                mma16816h(da[1], a1, b0);
                mma16816h(da[3], a0, b0 + 2);
                mma16816h(da[4], a1, b0 + 2);
                if (full) {
                    unsigned b1[4];
                    ldsm4(b1, Bt0 + 16384 + boff);
                    mma16816h(da[2], a0, b1);
                    mma16816h(da[5], a0, b1 + 2);
                }
            }
            // odd ks = 2*kp+1
            {
                unsigned kb = (unsigned)((2 * kp + 1) << 5);
                unsigned aoff = abase_off + ((kb + achunk) ^ asw);
                unsigned boff = bbase_off + ((kb + bchunk) ^ bsw);
                unsigned a0[4], a1[4], b0[4];
                ldsm4(a0, Abase + aoff);
                ldsm4(a1, Abase + 32768 + aoff);
                ldsm4(b0, Bt0 + boff);
                mma16816h(db[0], a0, b0);
                mma16816h(db[1], a1, b0);
                mma16816h(db[3], a0, b0 + 2);
                mma16816h(db[4], a1, b0 + 2);
                if (full) {
                    unsigned b1[4];
                    ldsm4(b1, Bt0 + 16384 + boff);
                    mma16816h(db[2], a0, b1);
                    mma16816h(db[5], a0, b1 + 2);
                }
            }
        }

        // ---- epilogue ----
        {
            float* dst; int dstride, dcol;
            if (tl < 8)       { dst = tbuf; dstride = 260; dcol = tl * 32; }
            else if (tl < 10) { dst = afb;  dstride = 66;  dcol = (tl - 8) * 32; }
            else if (tl < 18) { dst = tbuf; dstride = 260; dcol = (tl - 10) * 32; }
            else              { dst = tbuf; dstride = 260; dcol = (tl - 18) * 32; }
#pragma unroll
            for (int j = 0; j < 2; j++) {
                float e0 = (da[j*3][0] + db[j*3][0]) + (da[j*3+1][0] + db[j*3+1][0]) + (da[j*3+2][0] + db[j*3+2][0]);
                float e1 = (da[j*3][1] + db[j*3][1]) + (da[j*3+1][1] + db[j*3+1][1]) + (da[j*3+2][1] + db[j*3+2][1]);
                float e2 = (da[j*3][2] + db[j*3][2]) + (da[j*3+1][2] + db[j*3+1][2]) + (da[j*3+2][2] + db[j*3+2][2]);
                float e3 = (da[j*3][3] + db[j*3][3]) + (da[j*3+1][3] + db[j*3+1][3]) + (da[j*3+2][3] + db[j*3+2][3]);
                int dc = dcol + nh16 + j * 8 + 2 * etig;
                *(float2*)(dst + (size_t)er0 * dstride + dc) =
                    make_float2(e0 + p_pi0[j].x + p_pj0[j].x + p_bb[j].x,
                                e1 + p_pi0[j].y + p_pj0[j].y + p_bb[j].y);
                *(float2*)(dst + (size_t)er1 * dstride + dc) =
                    make_float2(e2 + p_pi1[j].x + p_pj1[j].x + p_bb[j].x,
                                e3 + p_pi1[j].y + p_pj1[j].y + p_bb[j].y);
            }
        }

        // ---- segment boundaries ----
        if (tl == 7) {
            __syncthreads();
#pragma unroll 1
            for (int rr = 0; rr < 8; rr++) {
                int row = rr * 8 + wid;
                const float* trow = tbuf + row * 260;
                float v[8], s = 0.f, qq = 0.f;
#pragma unroll
                for (int j = 0; j < 8; j++) {
                    float xv = fmaxf(trow[lane + j * 32], 0.f);
                    v[j] = xv; s += xv; qq += xv * xv;
                }
                s = warp_sum(s); qq = warp_sum(qq);
                float mu = s * inv256, rstd = rsqrtf(qq * inv256 - mu * mu + EPS);
                float* o = out + 524288 + ((size_t)n * 64 + row) * 256;
#pragma unroll
                for (int j = 0; j < 8; j++) {
                    int c = lane + j * 32;
                    o[c] = (v[j] - mu) * rstd * gif[c] + beif[c];
                }
            }
        }
        if (tl == 17) {
            __syncthreads();
#pragma unroll 1
            for (int rr = 0; rr < 8; rr++) {
                int row = rr * 8 + wid;
                {
                    float* ar = afb + row * 66;
                    float x0 = fmaxf(ar[lane], 0.f), x1 = fmaxf(ar[32 + lane], 0.f);
                    float s = warp_sum(x0 + x1), qq = warp_sum(x0 * x0 + x1 * x1);
                    float mu = s * inv64, rstd = rsqrtf(qq * inv64 - mu * mu + EPS);
                    ar[lane] = (x0 - mu) * rstd * gatt[lane] + beatt[lane];
                    ar[32 + lane] = (x1 - mu) * rstd * gatt[32 + lane] + beatt[32 + lane];
                }
                {
                    float* trow = tbuf + row * 260;
                    float v[8], s = 0.f, qq = 0.f;
#pragma unroll
                    for (int j = 0; j < 8; j++) {
                        float xv = fmaxf(trow[lane + j * 32], 0.f);
                        v[j] = xv; s += xv; qq += xv * xv;
                    }
                    s = warp_sum(s); qq = warp_sum(qq);
                    float mu = s * inv256, rstd = rsqrtf(qq * inv256 - mu * mu + EPS);
#pragma unroll
                    for (int j = 0; j < 8; j++) {
                        int c = lane + j * 32;
                        trow[c] = (v[j] - mu) * rstd * g1[c] + be1[c];
                    }
                }
            }
            __syncthreads();
            // rewrite A = h1 (2 fp16 images)
            {
                int row = t >> 2, k0 = (t & 3) * 64;
                const float* src = tbuf + row * 260 + k0;
#pragma unroll
                for (int c = 0; c < 8; c++) {
                    float4 v0 = *(const float4*)(src + c * 8);
                    float4 v1 = *(const float4*)(src + c * 8 + 4);
                    uint4 i0, i1;
                    split2h(v0.x, v0.y, i0.x, i1.x);
                    split2h(v0.z, v0.w, i0.y, i1.y);
                    split2h(v1.x, v1.y, i0.z, i1.z);
                    split2h(v1.z, v1.w, i0.w, i1.w);
                    unsigned off = (unsigned)(row * 512 + (((k0 + c * 8) * 2) ^ ((row & 7) << 4)));
                    *(uint4*)(Agen + off) = i0;
                    *(uint4*)(Agen + 32768 + off) = i1;
                }
            }
            __syncthreads();
        }
    }
    __syncthreads();

    // ---- Phase 4: h2 = LN(relu(t2)); logits -> slog ----
#pragma unroll 1
    for (int rr = 0; rr < 8; rr++) {
        int row = rr * 8 + wid;
        const float* trow = tbuf + row * 260;
        float v[8], s = 0.f, qq = 0.f;
#pragma unroll
        for (int j = 0; j < 8; j++) {
            float xv = fmaxf(trow[lane + j * 32], 0.f);
            v[j] = xv; s += xv; qq += xv * xv;
        }
        s = warp_sum(s); qq = warp_sum(qq);
        float mu = s * inv256, rstd = rsqrtf(qq * inv256 - mu * mu + EPS);
        float l0 = 0.f, l1 = 0.f, l2 = 0.f, l3 = 0.f;
#pragma unroll
        for (int j = 0; j < 8; j++) {
            int c = lane + j * 32;
            float y = (v[j] - mu) * rstd * g2[c] + be2[c];
            float4 wp = *(const float4*)(wpre + (size_t)c * 4);
            l0 += y * wp.x; l1 += y * wp.y; l2 += y * wp.z; l3 += y * wp.w;
        }
        l0 = warp_sum(l0); l1 = warp_sum(l1); l2 = warp_sum(l2); l3 = warp_sum(l3);
        if (lane == 0) {
            bool mk = mask[n * 64 + row] != 0;
            slog[row * 4 + 0] = mk ? NEG : (l0 + bpre[0]);
            slog[row * 4 + 1] = mk ? NEG : (l1 + bpre[1]);
            slog[row * 4 + 2] = mk ? NEG : (l2 + bpre[2]);
            slog[row * 4 + 3] = mk ? NEG : (l3 + bpre[3]);
        }
    }
    __syncthreads();

    // ---- Phase 5: per-head top-16 softmax ----
    if (wid < 4) {
        int h = wid;
        float v0 = slog[lane * 4 + h], v1 = slog[(32 + lane) * 4 + h];
        float c0 = v0, c1 = v1;
        float thr = NEG, maxv = NEG;
#pragma unroll 1
        for (int it = 0; it < 16; it++) {
            float loc = fmaxf(c0, c1);
            float m = warp_max(loc);
            if (it == 0) maxv = m;
            if (m == NEG) break;
            thr = m;
            unsigned bl = __ballot_sync(0xffffffffu, loc == m);
            int src = __ffs(bl) - 1;
            if (lane == src) { if (c0 == m) c0 = NEG; else c1 = NEG; }
        }
        float e0 = (v0 >= thr) ? expf(v0 - maxv) : 0.f;
        float e1 = (v1 >= thr) ? expf(v1 - maxv) : 0.f;
        float inv = 1.f / warp_sum(e0 + e1);
        wsm[h * 64 + lane] = e0 * inv;
        wsm[h * 64 + 32 + lane] = e1 * inv;
    }
    __syncthreads();

    // ---- Phase 6: agg[d,h] = sum_m w[h,m] * af[m,d] ----
    {
        int d = t >> 2, h = t & 3;
        float s = 0.f;
#pragma unroll
        for (int m = 0; m < 64; m++) s += wsm[h * 64 + m] * afb[m * 66 + d];
        aggs[t] = s;
    }
    __syncthreads();

    // ---- Phase 7: x_out = LN(relu(agg @ wg + bg)) ----
    {
        float v0a = 0.f, v1a = 0.f, v2a = 0.f, v3a = 0.f;
        float v4a = 0.f, v5a = 0.f, v6a = 0.f, v7a = 0.f;
#pragma unroll 4
        for (int k = 0; k < 256; k += 8) {
            v0a += aggs[k]     * wg[(size_t)k * 256 + t];
            v1a += aggs[k + 1] * wg[(size_t)(k + 1) * 256 + t];
            v2a += aggs[k + 2] * wg[(size_t)(k + 2) * 256 + t];
            v3a += aggs[k + 3] * wg[(size_t)(k + 3) * 256 + t];
            v4a += aggs[k + 4] * wg[(size_t)(k + 4) * 256 + t];
            v5a += aggs[k + 5] * wg[(size_t)(k + 5) * 256 + t];
            v6a += aggs[k + 6] * wg[(size_t)(k + 6) * 256 + t];
            v7a += aggs[k + 7] * wg[(size_t)(k + 7) * 256 + t];
        }
        float v = fmaxf(((v0a + v1a) + (v2a + v3a)) + ((v4a + v5a) + (v6a + v7a)) + bg[t], 0.f);
        float s = warp_sum(v), qq = warp_sum(v * v);
        if (lane == 0) { red[wid] = s; red[8 + wid] = qq; }
        __syncthreads();
        if (t < 32) {
            float a = (lane < 8) ? red[lane] : 0.f;
            float b = (lane < 8) ? red[8 + lane] : 0.f;
#pragma unroll
            for (int o = 4; o; o >>= 1) {
                a += __shfl_xor_sync(0xffffffffu, a, o);
                b += __shfl_xor_sync(0xffffffffu, b, o);
            }
            if (lane == 0) { red[0] = a; red[8] = b; }
        }
        __syncthreads();
        float mu = red[0] * inv256, rstd = rsqrtf(red[8] * inv256 - mu * mu + EPS);
        float y = (v - mu) * rstd * gg[t] + beg[t];
        out[(size_t)n * 256 + t] = y;
        out[34078720ull + (size_t)n * 256 + t] = y;
    }
}

// ---------------- launch ----------------
extern "C" void kernel_launch(void* const* d_in, const int* in_sizes, int n_in,
                              void* d_out, int out_size) {
    const float* x = (const float*)d_in[0];
    const float* iff = (const float*)d_in[1];
    const int* mask = (const int*)d_in[2];
    const int* ai = (const int*)d_in[3];
    const int* aj = (const int*)d_in[4];
    const float* w1 = (const float*)d_in[5], *b1 = (const float*)d_in[6];
    const float* g1 = (const float*)d_in[7], *be1 = (const float*)d_in[8];
    const float* w2 = (const float*)d_in[9], *b2 = (const float*)d_in[10];
    const float* g2 = (const float*)d_in[11], *be2 = (const float*)d_in[12];
    const float* wpre = (const float*)d_in[13], *bpre = (const float*)d_in[14];
    const float* watt = (const float*)d_in[15], *batt = (const float*)d_in[16];
    const float* gatt = (const float*)d_in[17], *beatt = (const float*)d_in[18];
    const float* wif = (const float*)d_in[19], *bif = (const float*)d_in[20];
    const float* gif = (const float*)d_in[21], *beif = (const float*)d_in[22];
    const float* wg = (const float*)d_in[23], *bg = (const float*)d_in[24];
    const float* gg = (const float*)d_in[25], *beg = (const float*)d_in[26];
    float* out = (float*)d_out;

    const int PS = (256 * 65 + 32 * 65) * 4;
    const int BS = 215552;
    cudaFuncSetAttribute(p_kernel, cudaFuncAttributeMaxDynamicSharedMemorySize, PS);
    cudaFuncSetAttribute(big_kernel, cudaFuncAttributeMaxDynamicSharedMemorySize, BS);

    dummy_kernel<<<1, 32>>>();
    pack_kernel<<<1152, 256>>>(w1, watt, wif, b1, batt, bif, w2);
    p_kernel<<<dim3(32, 2, 3), 256, PS>>>(x);
    big_kernel<<<2048, 256, BS>>>(iff, ai, aj, g1, be1, gatt, beatt, gif, beif,
                                  b2, g2, be2, wpre, bpre, mask,
                                  wg, bg, gg, beg, out);
}

// round 15
// speedup vs baseline: 1.6813x; 1.1243x over previous
#include <cuda_runtime.h>
#include <cuda_fp16.h>
#include <cstdint>
#include <cstddef>

#define NN 2048
#define EPS 1e-5f

// ---------------- device scratch ----------------
__device__ float g_Wcat[512 * 576];
__device__ float g_bcat[576];
__device__ float g_P[2 * NN * 576];
__device__ __align__(16) __half g_Bt[26 * 16384];  // 26 tiles x (hi 16KB | lo 16KB)

__device__ __forceinline__ float warp_sum(float v) {
#pragma unroll
    for (int o = 16; o; o >>= 1) v += __shfl_xor_sync(0xffffffffu, v, o);
    return v;
}
__device__ __forceinline__ float warp_max(float v) {
#pragma unroll
    for (int o = 16; o; o >>= 1) v = fmaxf(v, __shfl_xor_sync(0xffffffffu, v, o));
    return v;
}

#define CP_COMMIT() asm volatile("cp.async.commit_group;" ::: "memory")
#define CP_WAIT0()  asm volatile("cp.async.wait_group 0;" ::: "memory")

__device__ __forceinline__ void ldsm4(unsigned r[4], unsigned addr) {
    asm volatile("ldmatrix.sync.aligned.m8n8.x4.shared.b16 {%0,%1,%2,%3}, [%4];"
                 : "=r"(r[0]), "=r"(r[1]), "=r"(r[2]), "=r"(r[3]) : "r"(addr));
}
__device__ __forceinline__ void mma16816h(float d[4], const unsigned a[4], const unsigned b[2]) {
    asm volatile("mma.sync.aligned.m16n8k16.row.col.f32.f16.f16.f32 "
                 "{%0,%1,%2,%3}, {%4,%5,%6,%7}, {%8,%9}, {%0,%1,%2,%3};"
                 : "+f"(d[0]), "+f"(d[1]), "+f"(d[2]), "+f"(d[3])
                 : "r"(a[0]), "r"(a[1]), "r"(a[2]), "r"(a[3]), "r"(b[0]), "r"(b[1]));
}

__device__ __forceinline__ void split2h(float a, float b, uint32_t& w0, uint32_t& w1) {
    __half a0 = __float2half_rn(a), b0 = __float2half_rn(b);
    __half a1 = __float2half_rn(a - __half2float(a0));
    __half b1 = __float2half_rn(b - __half2float(b0));
    w0 = ((uint32_t)__half_as_ushort(b0) << 16) | (uint32_t)__half_as_ushort(a0);
    w1 = ((uint32_t)__half_as_ushort(b1) << 16) | (uint32_t)__half_as_ushort(a1);
}

// 32-col tiles: 0-7 new_if(gc 320..575), 8-9 att(gc 256..319), 10-17 h1(gc 0..255), 18-25 w2
__device__ __host__ __forceinline__ int tile_gc(int tl) {
    return (tl < 8) ? 320 + tl * 32 : (tl < 10) ? 256 + (tl - 8) * 32
          : (tl < 18) ? (tl - 10) * 32 : (tl - 18) * 32;
}

// per-warp epilogue for a full M16xN32 tile slice
__device__ __forceinline__ void epilogue_tile(int tl, float acc[4][4],
        float* tbuf, float* afb, const int* idxs, const float* b2,
        int etig, int er0, int er1) {
    float* dst; int dstride, dcol;
    if (tl < 8)       { dst = tbuf; dstride = 260; dcol = tl * 32; }
    else if (tl < 10) { dst = afb;  dstride = 66;  dcol = (tl - 8) * 32; }
    else if (tl < 18) { dst = tbuf; dstride = 260; dcol = (tl - 10) * 32; }
    else              { dst = tbuf; dstride = 260; dcol = (tl - 18) * 32; }
    int gc = tile_gc(tl);
    if (tl < 18) {
        const float* pia = g_P + (size_t)idxs[er0] * 576;
        const float* pja = g_P + (size_t)NN * 576 + (size_t)idxs[64 + er0] * 576;
        const float* pib = g_P + (size_t)idxs[er1] * 576;
        const float* pjb = g_P + (size_t)NN * 576 + (size_t)idxs[64 + er1] * 576;
#pragma unroll
        for (int j = 0; j < 4; j++) {
            int lc = j * 8 + 2 * etig;
            int colg = gc + lc;
            float2 bb  = *(const float2*)(g_bcat + colg);
            float2 pi0 = *(const float2*)(pia + colg);
            float2 pj0 = *(const float2*)(pja + colg);
            float2 pi1 = *(const float2*)(pib + colg);
            float2 pj1 = *(const float2*)(pjb + colg);
            *(float2*)(dst + (size_t)er0 * dstride + dcol + lc) =
                make_float2(acc[j][0] + pi0.x + pj0.x + bb.x,
                            acc[j][1] + pi0.y + pj0.y + bb.y);
            *(float2*)(dst + (size_t)er1 * dstride + dcol + lc) =
                make_float2(acc[j][2] + pi1.x + pj1.x + bb.x,
                            acc[j][3] + pi1.y + pj1.y + bb.y);
        }
    } else {
#pragma unroll
        for (int j = 0; j < 4; j++) {
            int lc = j * 8 + 2 * etig;
            float2 bb = *(const float2*)(b2 + gc + lc);
            *(float2*)(dst + (size_t)er0 * dstride + dcol + lc) =
                make_float2(acc[j][0] + bb.x, acc[j][1] + bb.y);
            *(float2*)(dst + (size_t)er1 * dstride + dcol + lc) =
                make_float2(acc[j][2] + bb.x, acc[j][3] + bb.y);
        }
    }
}

__global__ void dummy_kernel() {}

// ---------------- K0: pack ----------------
__global__ void pack_kernel(const float* __restrict__ w1, const float* __restrict__ watt,
                            const float* __restrict__ wif, const float* __restrict__ b1,
                            const float* __restrict__ batt, const float* __restrict__ bif,
                            const float* __restrict__ w2) {
    int idx = blockIdx.x * blockDim.x + threadIdx.x;
    if (idx < 512 * 576) {
        int r = idx / 576, c = idx - r * 576;
        g_Wcat[idx] = (c < 256) ? w1[r * 256 + c]
                     : (c < 320) ? watt[r * 64 + (c - 256)]
                                 : wif[r * 256 + (c - 320)];
    }
    if (idx < 576)
        g_bcat[idx] = (idx < 256) ? b1[idx] : (idx < 320) ? batt[idx - 256] : bif[idx - 320];
    if (idx < 26 * 8192) {
        int tl = idx >> 13, rr = idx & 8191;
        int n = rr >> 8, k = rr & 255;
        float w;
        if (tl < 18) {
            int c = tile_gc(tl) + n, r = 512 + k;
            w = (c < 256) ? w1[r * 256 + c]
               : (c < 320) ? watt[r * 64 + (c - 256)]
                           : wif[r * 256 + (c - 320)];
        } else {
            w = w2[k * 256 + (tl - 18) * 32 + n];
        }
        __half v0 = __float2half_rn(w);
        __half v1 = __float2half_rn(w - __half2float(v0));
        int byte = n * 512 + ((k * 2) ^ ((n & 7) << 4));
        size_t base = (size_t)tl * 16384 + (byte >> 1);
        g_Bt[base] = v0;
        g_Bt[base + 8192] = v1;
    }
}

// ---------------- K1: P = x @ Wcat(part) ----------------
__device__ __forceinline__ void micro_fma32(const float* __restrict__ ap,
                                            const float* __restrict__ bp, float acc[4][4]) {
#pragma unroll 8
    for (int k = 0; k < 32; k++) {
        const float* apk = ap + k * 65;
        const float* bpk = bp + k * 65;
        float a0 = apk[0], a1 = apk[1], a2 = apk[2], a3 = apk[3];
        float b0 = bpk[0], b1 = bpk[1], b2 = bpk[2], b3 = bpk[3];
        acc[0][0] += a0*b0; acc[0][1] += a0*b1; acc[0][2] += a0*b2; acc[0][3] += a0*b3;
        acc[1][0] += a1*b0; acc[1][1] += a1*b1; acc[1][2] += a1*b2; acc[1][3] += a1*b3;
        acc[2][0] += a2*b0; acc[2][1] += a2*b1; acc[2][2] += a2*b2; acc[2][3] += a2*b3;
        acc[3][0] += a3*b0; acc[3][1] += a3*b1; acc[3][2] += a3*b2; acc[3][3] += a3*b3;
    }
}
__global__ void __launch_bounds__(256) p_kernel(const float* __restrict__ x) {
    extern __shared__ float sm[];
    float* xs = sm;
    float* wsh = xs + 256 * 65;
    int nb = blockIdx.x, part = blockIdx.y, cg = blockIdx.z;
    int t = threadIdx.x, ty = t >> 4, tx = t & 15;
    {
        int row = t >> 2, k0 = (t & 3) * 64;
        const float* src = x + (size_t)(nb * 64 + row) * 256 + k0;
#pragma unroll
        for (int k = 0; k < 64; k += 4) {
            float4 v = *(const float4*)(src + k);
            xs[(k0+k)*65+row]=v.x; xs[(k0+k+1)*65+row]=v.y;
            xs[(k0+k+2)*65+row]=v.z; xs[(k0+k+3)*65+row]=v.w;
        }
    }
    __syncthreads();
    for (int cc = cg * 3; cc < cg * 3 + 3; cc++) {
        float acc[4][4] = {};
        for (int kp = 0; kp < 8; kp++) {
            {
                int k = t >> 3, cb = (t & 7) * 8;
                const float* src = g_Wcat + (size_t)(part*256 + kp*32 + k)*576 + cc*64 + cb;
                float4 v0 = *(const float4*)src, v1 = *(const float4*)(src + 4);
                float* d = wsh + k*65 + cb;
                d[0]=v0.x; d[1]=v0.y; d[2]=v0.z; d[3]=v0.w;
                d[4]=v1.x; d[5]=v1.y; d[6]=v1.z; d[7]=v1.w;
            }
            __syncthreads();
            micro_fma32(xs + kp*32*65 + ty*4, wsh + tx*4, acc);
            __syncthreads();
        }
#pragma unroll
        for (int ri = 0; ri < 4; ri++) {
            float4 v = make_float4(acc[ri][0], acc[ri][1], acc[ri][2], acc[ri][3]);
            *(float4*)(g_P + (size_t)part*NN*576 + (size_t)(nb*64 + ty*4 + ri)*576 + cc*64 + tx*4) = v;
        }
    }
}

// ---------------- K2: fused per-site kernel — 13 paired-tile phases, N32/warp ----------------
// smem (bytes): [16..528) idxs; A imgs at 1024 / 33792 (32KB each);
// B pair bufs 66560 / 99328 (32KB each); tbuf 132096 [64][260]; afb 198656 [64][66].
__global__ void __launch_bounds__(256) big_kernel(
    const float* __restrict__ IF, const int* __restrict__ ai, const int* __restrict__ aj,
    const float* __restrict__ g1, const float* __restrict__ be1,
    const float* __restrict__ gatt, const float* __restrict__ beatt,
    const float* __restrict__ gif, const float* __restrict__ beif,
    const float* __restrict__ b2, const float* __restrict__ g2, const float* __restrict__ be2,
    const float* __restrict__ wpre, const float* __restrict__ bpre,
    const int* __restrict__ mask,
    const float* __restrict__ wg, const float* __restrict__ bg,
    const float* __restrict__ gg, const float* __restrict__ beg,
    float* __restrict__ out) {
    extern __shared__ char smem[];
    const unsigned sb = (unsigned)__cvta_generic_to_shared(smem);
    int* idxs = (int*)(smem + 16);
    char* Agen = smem + 1024;
    const unsigned Abase = sb + 1024;
    const unsigned Bb[2] = { sb + 66560, sb + 99328 };
    float* tbuf = (float*)(smem + 132096);   // [64][260]
    float* afb  = (float*)(smem + 198656);   // [64][66]
    float* slog = (float*)(smem + 66560);    // aliases, used after GEMMs
    float* wsm  = (float*)(smem + 67584);
    float* aggs = (float*)(smem + 68608);
    float* red  = (float*)(smem + 69632);

    const int n = blockIdx.x, t = threadIdx.x;
    const int lane = t & 31, wid = t >> 5;
    const int mrow0 = (wid >> 1) << 4;       // M16 group (warps share per tsel)
    const int tsel = wid & 1;                // which tile of the pair
    const float NEG = __int_as_float(0xff800000);
    const float inv256 = 1.f / 256.f, inv64 = 1.f / 64.f;

    // ldmatrix geometry: A fragment (m16k16)
    const int arow = mrow0 + (lane & 15);
    const unsigned abase_off = (unsigned)(arow * 512);
    const unsigned asw = (unsigned)((arow & 7) << 4);
    const unsigned achunk = (unsigned)((lane >> 4) << 4);
    // B fragments (two n16k16 blocks of the warp's tile)
    const int brow0 = ((lane >> 4) << 3) + (lane & 7);
    const unsigned bbase0 = (unsigned)(brow0 * 512);
    const unsigned bsw = (unsigned)((brow0 & 7) << 4);
    const unsigned bchunk = (unsigned)(((lane >> 3) & 1) << 4);
    // epilogue geometry
    const int etig = lane & 3;
    const int er0 = mrow0 + (lane >> 2), er1 = er0 + 8;

    if (t < 64) { idxs[t] = ai[n * 64 + t]; idxs[64 + t] = aj[n * 64 + t]; }

    // pre-issue B loads for phase 0 (tiles 0,1; hi images only)
    {
#pragma unroll
        for (int tt = 0; tt < 2; tt++) {
            const char* src = (const char*)g_Bt + (size_t)tt * 32768;
            unsigned dstb = Bb[tt];
#pragma unroll
            for (int i = 0; i < 4; i++) {
                unsigned off = (unsigned)(i * 4096 + t * 16);
                asm volatile("cp.async.cg.shared.global [%0], [%1], 16;" :: "r"(dstb + off), "l"(src + off) : "memory");
            }
        }
        CP_COMMIT();
    }

    // convert IF -> A (2 fp16 images, swizzled)
    {
        int row = t >> 2, k0 = (t & 3) * 64;
        const float* src = IF + (size_t)(n * 64 + row) * 256 + k0;
#pragma unroll
        for (int c = 0; c < 8; c++) {
            float4 v0 = *(const float4*)(src + c * 8);
            float4 v1 = *(const float4*)(src + c * 8 + 4);
            uint4 i0, i1;
            split2h(v0.x, v0.y, i0.x, i1.x);
            split2h(v0.z, v0.w, i0.y, i1.y);
            split2h(v1.x, v1.y, i0.z, i1.z);
            split2h(v1.z, v1.w, i0.w, i1.w);
            unsigned off = (unsigned)(row * 512 + (((k0 + c * 8) * 2) ^ ((row & 7) << 4)));
            *(uint4*)(Agen + off) = i0;
            *(uint4*)(Agen + 32768 + off) = i1;
        }
    }

    // ================= 13 paired-tile phases =================
    float acc[4][4];
#pragma unroll 1
    for (int ph = 0; ph < 13; ph++) {
        __syncthreads();    // all warps done with mma(ph-1)'s B reads
        if (ph > 0) {
            int t0 = 2 * ph;
            int nch = (t0 >= 10) ? 8 : 4;
#pragma unroll 1
            for (int tt = 0; tt < 2; tt++) {
                const char* src = (const char*)g_Bt + (size_t)(t0 + tt) * 32768;
                unsigned dstb = Bb[tt];
#pragma unroll 1
                for (int i = 0; i < nch; i++) {
                    unsigned off = (unsigned)(i * 4096 + t * 16);
                    asm volatile("cp.async.cg.shared.global [%0], [%1], 16;" :: "r"(dstb + off), "l"(src + off) : "memory");
                }
            }
            CP_COMMIT();
            // deferred epilogue of previous phase (overlaps B-load latency)
            epilogue_tile(2 * (ph - 1) + tsel, acc, tbuf, afb, idxs, b2, etig, er0, er1);
        }

        // ---- segment boundaries ----
        if (ph == 4) {
            __syncthreads();   // new_if (tiles 0-7) fully in tbuf
#pragma unroll 1
            for (int rr = 0; rr < 8; rr++) {
                int row = rr * 8 + wid;
                const float* trow = tbuf + row * 260;
                float v[8], s = 0.f, qq = 0.f;
#pragma unroll
                for (int j = 0; j < 8; j++) {
                    float xv = fmaxf(trow[lane + j * 32], 0.f);
                    v[j] = xv; s += xv; qq += xv * xv;
                }
                s = warp_sum(s); qq = warp_sum(qq);
                float mu = s * inv256, rstd = rsqrtf(qq * inv256 - mu * mu + EPS);
                float* o = out + 524288 + ((size_t)n * 64 + row) * 256;
#pragma unroll
                for (int j = 0; j < 8; j++) {
                    int c = lane + j * 32;
                    o[c] = (v[j] - mu) * rstd * gif[c] + beif[c];
                }
            }
        }
        if (ph == 9) {
            __syncthreads();   // att + h1 fully written
#pragma unroll 1
            for (int rr = 0; rr < 8; rr++) {
                int row = rr * 8 + wid;
                {
                    float* ar = afb + row * 66;
                    float x0 = fmaxf(ar[lane], 0.f), x1 = fmaxf(ar[32 + lane], 0.f);
                    float s = warp_sum(x0 + x1), qq = warp_sum(x0 * x0 + x1 * x1);
                    float mu = s * inv64, rstd = rsqrtf(qq * inv64 - mu * mu + EPS);
                    ar[lane] = (x0 - mu) * rstd * gatt[lane] + beatt[lane];
                    ar[32 + lane] = (x1 - mu) * rstd * gatt[32 + lane] + beatt[32 + lane];
                }
                {
                    float* trow = tbuf + row * 260;
                    float v[8], s = 0.f, qq = 0.f;
#pragma unroll
                    for (int j = 0; j < 8; j++) {
                        float xv = fmaxf(trow[lane + j * 32], 0.f);
                        v[j] = xv; s += xv; qq += xv * xv;
                    }
                    s = warp_sum(s); qq = warp_sum(qq);
                    float mu = s * inv256, rstd = rsqrtf(qq * inv256 - mu * mu + EPS);
#pragma unroll
                    for (int j = 0; j < 8; j++) {
                        int c = lane + j * 32;
                        trow[c] = (v[j] - mu) * rstd * g1[c] + be1[c];
                    }
                }
            }
            __syncthreads();
            // rewrite A = h1 (2 fp16 images)
            {
                int row = t >> 2, k0 = (t & 3) * 64;
                const float* src = tbuf + row * 260 + k0;
#pragma unroll
                for (int c = 0; c < 8; c++) {
                    float4 v0 = *(const float4*)(src + c * 8);
                    float4 v1 = *(const float4*)(src + c * 8 + 4);
                    uint4 i0, i1;
                    split2h(v0.x, v0.y, i0.x, i1.x);
                    split2h(v0.z, v0.w, i0.y, i1.y);
                    split2h(v1.x, v1.y, i0.z, i1.z);
                    split2h(v1.z, v1.w, i0.w, i1.w);
                    unsigned off = (unsigned)(row * 512 + (((k0 + c * 8) * 2) ^ ((row & 7) << 4)));
                    *(uint4*)(Agen + off) = i0;
                    *(uint4*)(Agen + 32768 + off) = i1;
                }
            }
        }

        CP_WAIT0();
        __syncthreads();   // B[ph] (and A rewrite) visible to all

        // ---- mma: M16 x N32 per warp over K=256 ----
        const bool fullp = (ph >= 5);
        const unsigned Bt0 = Bb[tsel];
#pragma unroll
        for (int q = 0; q < 4; q++)
#pragma unroll
            for (int c = 0; c < 4; c++) acc[q][c] = 0.f;
#pragma unroll 4
        for (int ks = 0; ks < 16; ks++) {
            unsigned kb = (unsigned)(ks << 5);
            unsigned aoff = abase_off + ((kb + achunk) ^ asw);
            unsigned boff = bbase0 + ((kb + bchunk) ^ bsw);
            unsigned a0[4], a1[4], bh0[4], bh1[4];
            ldsm4(a0, Abase + aoff);
            ldsm4(a1, Abase + 32768 + aoff);
            ldsm4(bh0, Bt0 + boff);
            ldsm4(bh1, Bt0 + 8192 + boff);
            mma16816h(acc[0], a0, bh0);
            mma16816h(acc[1], a0, bh0 + 2);
            mma16816h(acc[2], a0, bh1);
            mma16816h(acc[3], a0, bh1 + 2);
            mma16816h(acc[0], a1, bh0);
            mma16816h(acc[1], a1, bh0 + 2);
            mma16816h(acc[2], a1, bh1);
            mma16816h(acc[3], a1, bh1 + 2);
            if (fullp) {
                unsigned bl0[4], bl1[4];
                ldsm4(bl0, Bt0 + 16384 + boff);
                ldsm4(bl1, Bt0 + 24576 + boff);
                mma16816h(acc[0], a0, bl0);
                mma16816h(acc[1], a0, bl0 + 2);
                mma16816h(acc[2], a0, bl1);
                mma16816h(acc[3], a0, bl1 + 2);
            }
        }
    }
    // final epilogue (phase 12 -> tiles 24/25)
    epilogue_tile(24 + tsel, acc, tbuf, afb, idxs, b2, etig, er0, er1);
    __syncthreads();

    // ---- Phase 4: h2 = LN(relu(t2)); logits -> slog ----
#pragma unroll 1
    for (int rr = 0; rr < 8; rr++) {
        int row = rr * 8 + wid;
        const float* trow = tbuf + row * 260;
        float v[8], s = 0.f, qq = 0.f;
#pragma unroll
        for (int j = 0; j < 8; j++) {
            float xv = fmaxf(trow[lane + j * 32], 0.f);
            v[j] = xv; s += xv; qq += xv * xv;
        }
        s = warp_sum(s); qq = warp_sum(qq);
        float mu = s * inv256, rstd = rsqrtf(qq * inv256 - mu * mu + EPS);
        float l0 = 0.f, l1 = 0.f, l2 = 0.f, l3 = 0.f;
#pragma unroll
        for (int j = 0; j < 8; j++) {
            int c = lane + j * 32;
            float y = (v[j] - mu) * rstd * g2[c] + be2[c];
            float4 wp = *(const float4*)(wpre + (size_t)c * 4);
            l0 += y * wp.x; l1 += y * wp.y; l2 += y * wp.z; l3 += y * wp.w;
        }
        l0 = warp_sum(l0); l1 = warp_sum(l1); l2 = warp_sum(l2); l3 = warp_sum(l3);
        if (lane == 0) {
            bool mk = mask[n * 64 + row] != 0;
            slog[row * 4 + 0] = mk ? NEG : (l0 + bpre[0]);
            slog[row * 4 + 1] = mk ? NEG : (l1 + bpre[1]);
            slog[row * 4 + 2] = mk ? NEG : (l2 + bpre[2]);
            slog[row * 4 + 3] = mk ? NEG : (l3 + bpre[3]);
        }
    }
    __syncthreads();

    // ---- Phase 5: per-head top-16 softmax ----
    if (wid < 4) {
        int h = wid;
        float v0 = slog[lane * 4 + h], v1 = slog[(32 + lane) * 4 + h];
        float c0 = v0, c1 = v1;
        float thr = NEG, maxv = NEG;
#pragma unroll 1
        for (int it = 0; it < 16; it++) {
            float loc = fmaxf(c0, c1);
            float m = warp_max(loc);
            if (it == 0) maxv = m;
            if (m == NEG) break;
            thr = m;
            unsigned bl = __ballot_sync(0xffffffffu, loc == m);
            int src = __ffs(bl) - 1;
            if (lane == src) { if (c0 == m) c0 = NEG; else c1 = NEG; }
        }
        float e0 = (v0 >= thr) ? expf(v0 - maxv) : 0.f;
        float e1 = (v1 >= thr) ? expf(v1 - maxv) : 0.f;
        float inv = 1.f / warp_sum(e0 + e1);
        wsm[h * 64 + lane] = e0 * inv;
        wsm[h * 64 + 32 + lane] = e1 * inv;
    }
    __syncthreads();

    // ---- Phase 6: agg[d,h] = sum_m w[h,m] * af[m,d] ----
    {
        int d = t >> 2, h = t & 3;
        float s = 0.f;
#pragma unroll
        for (int m = 0; m < 64; m++) s += wsm[h * 64 + m] * afb[m * 66 + d];
        aggs[t] = s;
    }
    __syncthreads();

    // ---- Phase 7: x_out = LN(relu(agg @ wg + bg)) ----
    {
        float v0a = 0.f, v1a = 0.f, v2a = 0.f, v3a = 0.f;
        float v4a = 0.f, v5a = 0.f, v6a = 0.f, v7a = 0.f;
#pragma unroll 4
        for (int k = 0; k < 256; k += 8) {
            v0a += aggs[k]     * wg[(size_t)k * 256 + t];
            v1a += aggs[k + 1] * wg[(size_t)(k + 1) * 256 + t];
            v2a += aggs[k + 2] * wg[(size_t)(k + 2) * 256 + t];
            v3a += aggs[k + 3] * wg[(size_t)(k + 3) * 256 + t];
            v4a += aggs[k + 4] * wg[(size_t)(k + 4) * 256 + t];
            v5a += aggs[k + 5] * wg[(size_t)(k + 5) * 256 + t];
            v6a += aggs[k + 6] * wg[(size_t)(k + 6) * 256 + t];
            v7a += aggs[k + 7] * wg[(size_t)(k + 7) * 256 + t];
        }
        float v = fmaxf(((v0a + v1a) + (v2a + v3a)) + ((v4a + v5a) + (v6a + v7a)) + bg[t], 0.f);
        float s = warp_sum(v), qq = warp_sum(v * v);
        if (lane == 0) { red[wid] = s; red[8 + wid] = qq; }
        __syncthreads();
        if (t < 32) {
            float a = (lane < 8) ? red[lane] : 0.f;
            float b = (lane < 8) ? red[8 + lane] : 0.f;
#pragma unroll
            for (int o = 4; o; o >>= 1) {
                a += __shfl_xor_sync(0xffffffffu, a, o);
                b += __shfl_xor_sync(0xffffffffu, b, o);
            }
            if (lane == 0) { red[0] = a; red[8] = b; }
        }
        __syncthreads();
        float mu = red[0] * inv256, rstd = rsqrtf(red[8] * inv256 - mu * mu + EPS);
        float y = (v - mu) * rstd * gg[t] + beg[t];
        out[(size_t)n * 256 + t] = y;
        out[34078720ull + (size_t)n * 256 + t] = y;
    }
}

// ---------------- launch ----------------
extern "C" void kernel_launch(void* const* d_in, const int* in_sizes, int n_in,
                              void* d_out, int out_size) {
    const float* x = (const float*)d_in[0];
    const float* iff = (const float*)d_in[1];
    const int* mask = (const int*)d_in[2];
    const int* ai = (const int*)d_in[3];
    const int* aj = (const int*)d_in[4];
    const float* w1 = (const float*)d_in[5], *b1 = (const float*)d_in[6];
    const float* g1 = (const float*)d_in[7], *be1 = (const float*)d_in[8];
    const float* w2 = (const float*)d_in[9], *b2 = (const float*)d_in[10];
    const float* g2 = (const float*)d_in[11], *be2 = (const float*)d_in[12];
    const float* wpre = (const float*)d_in[13], *bpre = (const float*)d_in[14];
    const float* watt = (const float*)d_in[15], *batt = (const float*)d_in[16];
    const float* gatt = (const float*)d_in[17], *beatt = (const float*)d_in[18];
    const float* wif = (const float*)d_in[19], *bif = (const float*)d_in[20];
    const float* gif = (const float*)d_in[21], *beif = (const float*)d_in[22];
    const float* wg = (const float*)d_in[23], *bg = (const float*)d_in[24];
    const float* gg = (const float*)d_in[25], *beg = (const float*)d_in[26];
    float* out = (float*)d_out;

    const int PS = (256 * 65 + 32 * 65) * 4;
    const int BS = 215552;
    cudaFuncSetAttribute(p_kernel, cudaFuncAttributeMaxDynamicSharedMemorySize, PS);
    cudaFuncSetAttribute(big_kernel, cudaFuncAttributeMaxDynamicSharedMemorySize, BS);

    dummy_kernel<<<1, 32>>>();
    pack_kernel<<<1152, 256>>>(w1, watt, wif, b1, batt, bif, w2);
    p_kernel<<<dim3(32, 2, 3), 256, PS>>>(x);
    big_kernel<<<2048, 256, BS>>>(iff, ai, aj, g1, be1, gatt, beatt, gif, beif,
                                  b2, g2, be2, wpre, bpre, mask,
                                  wg, bg, gg, beg, out);
}